// round 1
// baseline (speedup 1.0000x reference)
#include <cuda_runtime.h>
#include <cuda_bf16.h>

// Problem constants
#define NNODE   16384
#define CDIM    48
#define KNN     9
#define BATCHSZ 4096

typedef unsigned long long u64;

// -------- scratch (device globals; no allocation allowed) --------
__device__ __align__(256) float g_xf[NNODE * CDIM];   // [N,48] node features
__device__ float g_sq[NNODE];                         // row squared norms
__device__ int   g_nbr[NNODE * KNN];                  // knn indices
__device__ int   g_deg[NNODE];                        // degree over src

// packed fp32x2 fma (sm_100+/sm_103a): 2 IEEE fp32 FMAs per instruction
__device__ __forceinline__ u64 fma2(u64 a, u64 b, u64 c) {
    u64 d;
    asm("fma.rn.f32x2 %0, %1, %2, %3;" : "=l"(d) : "l"(a), "l"(b), "l"(c));
    return d;
}
__device__ __forceinline__ void unpack2(u64 v, float& lo, float& hi) {
    asm("mov.b64 {%0, %1}, %2;" : "=f"(lo), "=f"(hi) : "l"(v));
}

// ============ kernel 1: [B,C,H,W] -> [N,C] transpose ============
__global__ __launch_bounds__(192) void transpose_kernel(const float* __restrict__ x) {
    int bh = blockIdx.x;            // b*64 + h, 256 blocks
    __shared__ float s[48][65];
    const float* src = x + (size_t)(bh >> 6) * 48 * 4096 + (bh & 63) * 64;
    for (int idx = threadIdx.x; idx < 48 * 64; idx += 192) {
        int c = idx >> 6, w = idx & 63;
        s[c][w] = src[c * 4096 + w];
    }
    __syncthreads();
    float* dst = g_xf + (size_t)bh * 64 * 48;
    for (int idx = threadIdx.x; idx < 48 * 64; idx += 192) {
        int w = idx / 48, c = idx - w * 48;
        dst[w * 48 + c] = s[c][w];
    }
}

// ============ kernel 2: row norms + zero deg ============
__global__ __launch_bounds__(256) void sq_kernel() {
    int i = blockIdx.x * 256 + threadIdx.x;   // 64 blocks
    if (i >= NNODE) return;
    const float4* r = (const float4*)(g_xf + (size_t)i * CDIM);
    float s = 0.f;
#pragma unroll
    for (int k = 0; k < 12; k++) {
        float4 v = r[k];
        s += v.x * v.x + v.y * v.y + v.z * v.z + v.w * v.w;
    }
    g_sq[i] = s;
    g_deg[i] = 0;
}

// ============ kernel 3: knn (top-9 smallest dist, lower-index ties) ============
// 256 blocks x 256 threads. Block owns 64 centers; 4 threads per center split
// the candidate sweep (interleaved rows within each 128-row smem tile).
__global__ __launch_bounds__(256) void knn_kernel() {
    __shared__ __align__(16) float stile[128 * 48];   // 24KB candidate tile
    __shared__ float ssq[128];
    __shared__ float smd[64 * 4 * KNN];               // partial dists
    __shared__ int   smi[64 * 4 * KNN];               // partial idxs

    const int tid  = threadIdx.x;
    const int il   = tid & 63;
    const int part = tid >> 6;
    const int i    = blockIdx.x * 64 + il;
    const int batch  = blockIdx.x >> 6;
    const int jbase  = batch << 12;
    const int jcount = (batch == 3) ? (BATCHSZ - 1) : BATCHSZ;  // exclude node 16383

    // center features in registers (as fp32x2 pairs)
    u64 xi2[24];
    {
        const ulonglong2* xr = (const ulonglong2*)(g_xf + (size_t)i * CDIM);
#pragma unroll
        for (int c = 0; c < 12; c++) {
            ulonglong2 v = xr[c];
            xi2[2 * c] = v.x; xi2[2 * c + 1] = v.y;
        }
    }
    const float sqi = g_sq[i];

    float d9[KNN]; int n9[KNN];
#pragma unroll
    for (int k = 0; k < KNN; k++) { d9[k] = 3.402823466e+38f; n9[k] = 0x7fffffff; }

    for (int jt = 0; jt < jcount; jt += 128) {
        const int rem = min(128, jcount - jt);
        // cooperative tile load (float4, layouts match: contiguous rows)
        {
            const int nf4 = rem * 12;
            const float4* src = (const float4*)(g_xf + (size_t)(jbase + jt) * CDIM);
            float4* dst = (float4*)stile;
            for (int f = tid; f < nf4; f += 256) dst[f] = src[f];
            if (tid < rem) ssq[tid] = g_sq[jbase + jt + tid];
        }
        __syncthreads();

        for (int r = part; r < rem; r += 4) {
            const ulonglong2* xj = (const ulonglong2*)(stile + r * 48);
            u64 a0 = 0, a1 = 0, a2 = 0, a3 = 0;
#pragma unroll
            for (int c = 0; c < 12; c += 2) {
                ulonglong2 v0 = xj[c];
                ulonglong2 v1 = xj[c + 1];
                a0 = fma2(xi2[2 * c],     v0.x, a0);
                a1 = fma2(xi2[2 * c + 1], v0.y, a1);
                a2 = fma2(xi2[2 * c + 2], v1.x, a2);
                a3 = fma2(xi2[2 * c + 3], v1.y, a3);
            }
            float l0, h0, l1, h1, l2, h2, l3, h3;
            unpack2(a0, l0, h0); unpack2(a1, l1, h1);
            unpack2(a2, l2, h2); unpack2(a3, l3, h3);
            float dot = ((l0 + h0) + (l1 + h1)) + ((l2 + h2) + (l3 + h3));
            float dist = (sqi + ssq[r]) - 2.0f * dot;

            if (dist < d9[8]) {   // strict < : ascending j keeps lowest index on ties
                d9[8] = dist; n9[8] = jbase + jt + r;
#pragma unroll
                for (int k = 8; k > 0; k--) {
                    if (d9[k] < d9[k - 1]) {
                        float td = d9[k]; d9[k] = d9[k - 1]; d9[k - 1] = td;
                        int   ti = n9[k]; n9[k] = n9[k - 1]; n9[k - 1] = ti;
                    }
                }
            }
        }
        __syncthreads();
    }

    // publish partials
    {
        const int base = (il * 4 + part) * KNN;
#pragma unroll
        for (int k = 0; k < KNN; k++) { smd[base + k] = d9[k]; smi[base + k] = n9[k]; }
    }
    __syncthreads();

    // 4-way lexicographic merge by (dist, idx), done by part-0 threads
    if (part == 0) {
        if (i == NNODE - 1) {
            // node 16383: alone in batch 4 -> self + 8 lowest-index -inf ties (0..7)
            g_nbr[i * KNN + 0] = NNODE - 1;
#pragma unroll
            for (int k = 1; k < KNN; k++) g_nbr[i * KNN + k] = k - 1;
        } else {
            int p[4] = {0, 0, 0, 0};
            for (int k = 0; k < KNN; k++) {
                float bd = 3.402823466e+38f; int bi = 0x7fffffff; int bq = 0;
#pragma unroll
                for (int q = 0; q < 4; q++) {
                    const int pq = p[q];
                    float dq = 3.402823466e+38f; int iq = 0x7fffffff;
                    if (pq < KNN) {
                        dq = smd[(il * 4 + q) * KNN + pq];
                        iq = smi[(il * 4 + q) * KNN + pq];
                    }
                    if (dq < bd || (dq == bd && iq < bi)) { bd = dq; bi = iq; bq = q; }
                }
                p[bq]++;
                g_nbr[i * KNN + k] = bi;
            }
        }
    }
}

// ============ kernel 4: degree over src ============
__global__ __launch_bounds__(256) void deg_kernel() {
    int e = blockIdx.x * 256 + threadIdx.x;
    if (e < NNODE * KNN) atomicAdd(&g_deg[g_nbr[e]], 1);
}

// ============ kernel 5: fused gather + (xf@W0 + tx1@W1 + b) + relu ============
// block = 384 threads = 8 rows x 48 output cols
__global__ __launch_bounds__(384) void out_kernel(const float* __restrict__ W0,
                                                  const float* __restrict__ W1,
                                                  const float* __restrict__ b,
                                                  float* __restrict__ out) {
    __shared__ float W0s[2304], W1s[2304], bs[48];
    __shared__ float sx[8][48], sg[8][48], sdin[8];
    const int tid = threadIdx.x;
    for (int k = tid; k < 2304; k += 384) { W0s[k] = W0[k]; W1s[k] = W1[k]; }
    if (tid < 48) bs[tid] = b[tid];

    const int row = tid / 48, o = tid % 48;
    const int i = blockIdx.x * 8 + row;

    sx[row][o] = g_xf[(size_t)i * 48 + o];
    float g = 0.f;
    const int* nb = &g_nbr[i * KNN];
#pragma unroll
    for (int k = 0; k < KNN; k++) {
        const int j = nb[k];
        const float dj = rsqrtf((float)g_deg[j]);
        g += dj * g_xf[(size_t)j * 48 + o];
    }
    sg[row][o] = g;
    if (o == 0) sdin[row] = rsqrtf((float)g_deg[i]);
    __syncthreads();

    float a0 = 0.f, a1 = 0.f;
#pragma unroll
    for (int c = 0; c < 48; c++) {
        a0 += sx[row][c] * W0s[c * 48 + o];
        a1 += sg[row][c] * W1s[c * 48 + o];
    }
    const float v = bs[o] + a0 - sdin[row] * a1;
    out[(size_t)i * 48 + o] = fmaxf(v, 0.f);
}

// ============ launch ============
extern "C" void kernel_launch(void* const* d_in, const int* in_sizes, int n_in,
                              void* d_out, int out_size) {
    const float* x  = (const float*)d_in[0];
    const float* W0 = (const float*)d_in[1];
    const float* W1 = (const float*)d_in[2];
    const float* b  = (const float*)d_in[3];
    float* out = (float*)d_out;

    transpose_kernel<<<256, 192>>>(x);
    sq_kernel<<<64, 256>>>();
    knn_kernel<<<256, 256>>>();
    deg_kernel<<<(NNODE * KNN + 255) / 256, 256>>>();
    out_kernel<<<NNODE / 8, 384>>>(W0, W1, b, out);
}